// round 1
// baseline (speedup 1.0000x reference)
#include <cuda_runtime.h>

#define DET     736
#define PAD     735
#define NODD    736        // number of odd-offset (nonzero) taps
#define XS_LEN  2240       // >= DET + 2*PAD + overrun slack, zero-padded
#define THREADS 92
#define TOUT    8

// Precomputed per-launch constants (device globals: no allocation)
__device__ float g_cw[DET];        // cosine fan-beam weights
__device__ float g_fz[NODD + 16];  // compacted odd taps: g_fz[j] = filt[2*j]
__device__ float g_fc;             // center tap filt[735]

typedef unsigned long long u64;

__device__ __forceinline__ u64 pk2(float a, float b) {
    u64 r; asm("mov.b64 %0, {%1, %2};" : "=l"(r) : "f"(a), "f"(b)); return r;
}
__device__ __forceinline__ void upk2(u64 v, float &a, float &b) {
    asm("mov.b64 {%0, %1}, %2;" : "=f"(a), "=f"(b) : "l"(v));
}
__device__ __forceinline__ void fma2(u64 &acc, u64 a, u64 b) {
    // packed fp32x2 FMA (sm_103a): 2 lane-FMAs per instruction
    asm("fma.rn.f32x2 %0, %1, %2, %0;" : "+l"(acc) : "l"(a), "l"(b));
}
// Full 5-bit XOR swizzle: warp accesses with 8-float lane stride hit distinct banks
__device__ __forceinline__ int swz(int i) { return i ^ ((i >> 5) & 31); }

__global__ void prep_kernel(const float* __restrict__ filt,
                            const int*   __restrict__ scale_p) {
    int i = threadIdx.x;
    int s_i = *scale_p;
    // scale may arrive as int32 or float32; small positive int => int encoding
    float scale = (s_i >= 1 && s_i <= 1024) ? (float)s_i : __int_as_float(s_i);
    if (i < DET) {
        // s_range = det_interval*(i-(det-1)/2)*scale/SDD ; cos_weight = SCD/1e4 * cos
        float s = ((float)i - 367.5f) * scale * 1.0e-3f;
        g_cw[i] = 0.05f * cosf(s);
    }
    if (i < NODD)                 g_fz[i] = filt[2 * i]; // odd-offset taps (t even)
    else if (i < NODD + 16)       g_fz[i] = 0.0f;
    if (i == 0)                   g_fc = filt[PAD];      // center tap
}

__global__ void __launch_bounds__(THREADS)
conv_kernel(const float* __restrict__ x, float* __restrict__ out) {
    __shared__ float xs[XS_LEN];
    __shared__ __align__(16) float fz[NODD + 16];

    const int row = blockIdx.x;
    const int tid = threadIdx.x;
    const float* __restrict__ xr = x + (size_t)row * DET;

    // Stage padded + cosine-weighted row into swizzled shared memory
    for (int i = tid; i < XS_LEN; i += THREADS) {
        float v = 0.0f;
        int k = i - PAD;
        if (k >= 0 && k < DET) v = xr[k] * g_cw[k];
        xs[swz(i)] = v;
    }
    for (int i = tid; i < NODD + 16; i += THREADS) fz[i] = g_fz[i];
    __syncthreads();

    const int d = tid * TOUT;   // 8 consecutive outputs per thread, d even
    const float fc = g_fc;

    // Init accumulators with the (odd-aligned) center tap: out[d+i] += fc * x[d+i]
    u64 acc[4];
#pragma unroll
    for (int q = 0; q < 4; ++q) {
        float a = fc * xs[swz(PAD + d + 2 * q)];
        float b = fc * xs[swz(PAD + d + 2 * q + 1)];
        acc[q] = pk2(a, b);
    }

    // Packed sliding window wp[s] = (xs[B+2s], xs[B+2s+1]), B = d + 2*j
#pragma unroll
    u64 wp[7];
#pragma unroll
    for (int s = 0; s < 7; ++s)
        wp[s] = pk2(xs[swz(d + 2 * s)], xs[swz(d + 2 * s + 1)]);

    int B = d;
#pragma unroll 1
    for (int j = 0; j < NODD; j += 4) {
        const float4 f4 = *(const float4*)&fz[j];
        u64 ff;
        ff = pk2(f4.x, f4.x);
        fma2(acc[0], ff, wp[0]); fma2(acc[1], ff, wp[1]);
        fma2(acc[2], ff, wp[2]); fma2(acc[3], ff, wp[3]);
        ff = pk2(f4.y, f4.y);
        fma2(acc[0], ff, wp[1]); fma2(acc[1], ff, wp[2]);
        fma2(acc[2], ff, wp[3]); fma2(acc[3], ff, wp[4]);
        ff = pk2(f4.z, f4.z);
        fma2(acc[0], ff, wp[2]); fma2(acc[1], ff, wp[3]);
        fma2(acc[2], ff, wp[4]); fma2(acc[3], ff, wp[5]);
        ff = pk2(f4.w, f4.w);
        fma2(acc[0], ff, wp[3]); fma2(acc[1], ff, wp[4]);
        fma2(acc[2], ff, wp[5]); fma2(acc[3], ff, wp[6]);
        // slide window forward by 4 pairs (8 scalars)
        wp[0] = wp[4]; wp[1] = wp[5]; wp[2] = wp[6];
        wp[3] = pk2(xs[swz(B + 14)], xs[swz(B + 15)]);
        wp[4] = pk2(xs[swz(B + 16)], xs[swz(B + 17)]);
        wp[5] = pk2(xs[swz(B + 18)], xs[swz(B + 19)]);
        wp[6] = pk2(xs[swz(B + 20)], xs[swz(B + 21)]);
        B += 8;
    }

    float2* __restrict__ orow = (float2*)(out + (size_t)row * DET);
#pragma unroll
    for (int q = 0; q < 4; ++q) {
        float a, b; upk2(acc[q], a, b);
        orow[(d >> 1) + q] = make_float2(a, b);
    }
}

extern "C" void kernel_launch(void* const* d_in, const int* in_sizes, int n_in,
                              void* d_out, int out_size) {
    const float* sino  = (const float*)d_in[0];
    const float* filt  = (const float*)d_in[1];
    const int*   scale = (const int*)d_in[2];
    float* out = (float*)d_out;

    int rows = in_sizes[0] / DET;   // 16*1*1152 = 18432

    prep_kernel<<<1, 768>>>(filt, scale);
    conv_kernel<<<rows, THREADS>>>(sino, out);
}

// round 2
// speedup vs baseline: 1.8360x; 1.8360x over previous
#include <cuda_runtime.h>

#define DET       736
#define TOUT      16
#define TPR       46          // threads per row (736 = 16*46)
#define THREADS   92          // 2 rows per block
#define PITCH     139         // u64 (float-pair) entries per plane
#define ROWSTRIDE 1118        // 8*PITCH = 1112, padded so ROWSTRIDE ≡ 14 (mod 16)
#define NPAIR     1112        // staged pairs per row (8*PITCH)
#define NODD      736

typedef unsigned long long u64;

// device-global scratch (no allocation allowed)
__device__ u64   g_fz2[NODD];     // splatted odd taps: (filt[2j], filt[2j])
__device__ float g_fc;            // center tap filt[735]

__device__ __forceinline__ u64 pk2(float a, float b) {
    u64 r; asm("mov.b64 %0, {%1, %2};" : "=l"(r) : "f"(a), "f"(b)); return r;
}
__device__ __forceinline__ void fma2(u64 &acc, u64 a, u64 b) {
    asm("fma.rn.f32x2 %0, %1, %2, %0;" : "+l"(acc) : "l"(a), "l"(b));
}

__global__ void prep_kernel(const float* __restrict__ filt) {
    int j = threadIdx.x;
    if (j < NODD) {
        float f = filt[2 * j];
        g_fz2[j] = pk2(f, f);
    }
    if (j == 0) g_fc = filt[735];
}

__device__ __forceinline__ void tapstep(u64 ff, u64* acc, const u64* w) {
#pragma unroll
    for (int q = 0; q < 8; ++q) fma2(acc[q], ff, w[q]);
}

__global__ void __launch_bounds__(THREADS)
conv_kernel(const float* __restrict__ x, float* __restrict__ out,
            const int* __restrict__ scale_p, int nrows) {
    // pair-plane layout: pair e (xs[2e], xs[2e+1]) stored at plane e&7, index e>>3
    // xs[i] = x[i-737] * cw[i-737]  (zero outside)
    __shared__ u64 xs2[2 * ROWSTRIDE];

    const int tid = threadIdx.x;
    const int bid = blockIdx.x;

    // decode scale (int32 or float32 encoding)
    int s_i = *scale_p;
    float scale = (s_i >= 1 && s_i <= 1024) ? (float)s_i : __int_as_float(s_i);
    const float kk = scale * 1.0e-3f;

    // ---- stage both rows (cosine-weighted, padded, pair-transposed) ----
    const int row_g0 = 2 * bid;
    const float* xr0 = x + (size_t)row_g0 * DET;
    const float* xr1 = xr0 + DET;
    const bool r1ok = (row_g0 + 1) < nrows;

    for (int e = tid; e < NPAIR; e += THREADS) {
        int base = ((e & 7) * PITCH) + (e >> 3);
        int p0 = 2 * e - 737;
        int p1 = p0 + 1;
        float w0 = 0.05f * __cosf(((float)p0 - 367.5f) * kk);
        float w1 = 0.05f * __cosf(((float)p1 - 367.5f) * kk);
        bool v0ok = (p0 >= 0) & (p0 < DET);
        bool v1ok = (p1 >= 0) & (p1 < DET);
        float a0 = v0ok ? xr0[p0] * w0 : 0.0f;
        float a1 = v1ok ? xr0[p1] * w1 : 0.0f;
        xs2[base] = pk2(a0, a1);
        float b0 = (v0ok && r1ok) ? xr1[p0] * w0 : 0.0f;
        float b1 = (v1ok && r1ok) ? xr1[p1] * w1 : 0.0f;
        xs2[ROWSTRIDE + base] = pk2(b0, b1);
    }
    __syncthreads();

    const int row = tid / TPR;            // 0 or 1
    const int tl  = tid - row * TPR;      // thread-in-row
    const u64* wbase = &xs2[row * ROWSTRIDE + tl];
    const float fc = g_fc;

    // ---- init accumulators with center tap: out[d] += fc * x[d] ----
    // x[d0+2q]   -> pair e=8tl+(368+q), comp 1 ; x[d0+2q+1] -> pair e=8tl+(369+q), comp 0
    u64 acc[8];
#pragma unroll
    for (int q = 0; q < 8; ++q) {
        int h0 = 368 + q, h1 = 369 + q;
        float a = fc * ((const float*)&wbase[(h0 & 7) * PITCH + (h0 >> 3)])[1];
        float b = fc * ((const float*)&wbase[(h1 & 7) * PITCH + (h1 >> 3)])[0];
        acc[q] = pk2(a, b);
    }

    // ---- sliding packed window: wp[s] = pair(h = jb + 1 + s) ----
    u64 wp[15];
    wp[0]  = wbase[1 * PITCH];     wp[1]  = wbase[2 * PITCH];
    wp[2]  = wbase[3 * PITCH];     wp[3]  = wbase[4 * PITCH];
    wp[4]  = wbase[5 * PITCH];     wp[5]  = wbase[6 * PITCH];
    wp[6]  = wbase[7 * PITCH];
    wp[7]  = wbase[0 * PITCH + 1]; wp[8]  = wbase[1 * PITCH + 1];
    wp[9]  = wbase[2 * PITCH + 1]; wp[10] = wbase[3 * PITCH + 1];

    const u64* wk = wbase;         // k-offset = jb>>3
    const u64* fp = g_fz2;

#pragma unroll 1
    for (int it = 0; it < NODD / 8; ++it) {
        // taps jb..jb+3
        tapstep(__ldg(fp + 0), acc, wp + 0);
        tapstep(__ldg(fp + 1), acc, wp + 1);
        tapstep(__ldg(fp + 2), acc, wp + 2);
        tapstep(__ldg(fp + 3), acc, wp + 3);
        // mid refill: h = jb+12..jb+15 -> planes 4..7, k = jb/8 + 1
        wp[11] = wk[4 * PITCH + 1];
        wp[12] = wk[5 * PITCH + 1];
        wp[13] = wk[6 * PITCH + 1];
        wp[14] = wk[7 * PITCH + 1];
        // taps jb+4..jb+7
        tapstep(__ldg(fp + 4), acc, wp + 4);
        tapstep(__ldg(fp + 5), acc, wp + 5);
        tapstep(__ldg(fp + 6), acc, wp + 6);
        tapstep(__ldg(fp + 7), acc, wp + 7);
        // shift by 8 and end refill: h = jb+16..jb+19 -> planes 0..3, k = jb/8 + 2
        wp[0] = wp[8];  wp[1] = wp[9];  wp[2] = wp[10]; wp[3] = wp[11];
        wp[4] = wp[12]; wp[5] = wp[13]; wp[6] = wp[14];
        wp[7]  = wk[0 * PITCH + 2];
        wp[8]  = wk[1 * PITCH + 2];
        wp[9]  = wk[2 * PITCH + 2];
        wp[10] = wk[3 * PITCH + 2];
        wk += 1;
        fp += 8;
    }

    // ---- store 16 outputs as 8 packed u64 ----
    int row_g = row_g0 + row;
    if (row_g < nrows) {
        u64* orow = (u64*)(out + (size_t)row_g * DET);
#pragma unroll
        for (int q = 0; q < 8; ++q) orow[8 * tl + q] = acc[q];
    }
}

extern "C" void kernel_launch(void* const* d_in, const int* in_sizes, int n_in,
                              void* d_out, int out_size) {
    const float* sino  = (const float*)d_in[0];
    const float* filt  = (const float*)d_in[1];
    const int*   scale = (const int*)d_in[2];
    float* out = (float*)d_out;

    int nrows = in_sizes[0] / DET;          // 18432
    int nblk  = (nrows + 1) / 2;            // 2 rows per block

    prep_kernel<<<1, 768>>>(filt);
    conv_kernel<<<nblk, THREADS>>>(sino, out, scale, nrows);
}

// round 3
// speedup vs baseline: 1.9470x; 1.0604x over previous
#include <cuda_runtime.h>

#define DET       736
#define TOUT      16
#define TPR       46          // threads per row (736 = 16*46)
#define THREADS   92          // 2 rows per block
#define PITCH     139         // u64 (float-pair) entries per plane
#define ROWSTRIDE 1118        // 8*PITCH=1112, padded so ROWSTRIDE ≡ 14 (mod 16)
#define NPAIR     1112        // staged pairs per row
#define NODD      736
#define NTAPPAD   768         // g_fz2 padded with zeros (loop reads to 751)

typedef unsigned long long u64;

__device__ u64   g_fz2[NTAPPAD];  // splatted odd taps: (filt[2j], filt[2j]); zero-padded
__device__ float g_fc;            // center tap filt[735]

__device__ __forceinline__ u64 pk2(float a, float b) {
    u64 r; asm("mov.b64 %0, {%1, %2};" : "=l"(r) : "f"(a), "f"(b)); return r;
}
__device__ __forceinline__ void fma2(u64 &acc, u64 a, u64 b) {
    asm("fma.rn.f32x2 %0, %1, %2, %0;" : "+l"(acc) : "l"(a), "l"(b));
}

__global__ void prep_kernel(const float* __restrict__ filt) {
    int j = threadIdx.x;
    if (j < NODD) {
        float f = filt[2 * j];
        g_fz2[j] = pk2(f, f);
    } else if (j < NTAPPAD) {
        g_fz2[j] = 0ull;
    }
    if (j == 0) g_fc = filt[735];
}

// tap j uses rotating window slots (S+q)&15, all compile-time
template <int S>
__device__ __forceinline__ void tapstep(u64 ff, u64* acc, const u64* w) {
#pragma unroll
    for (int q = 0; q < 8; ++q) fma2(acc[q], ff, w[(S + q) & 15]);
}

__global__ void __launch_bounds__(THREADS)
conv_kernel(const float* __restrict__ x, float* __restrict__ out,
            const int* __restrict__ scale_p, int nrows) {
    // pair-plane layout: pair e = (xs[2e], xs[2e+1]) at plane e&7, index e>>3
    // xs[i] = x[i-737] * cw[i-737]  (zero outside)
    __shared__ u64 xs2[2 * ROWSTRIDE];

    const int tid = threadIdx.x;
    const int bid = blockIdx.x;

    int s_i = *scale_p;
    float scale = (s_i >= 1 && s_i <= 1024) ? (float)s_i : __int_as_float(s_i);
    const float kk = scale * 1.0e-3f;

    // ---- stage both rows (cosine-weighted, padded, pair-transposed) ----
    const int row_g0 = 2 * bid;
    const float* xr0 = x + (size_t)row_g0 * DET;
    const float* xr1 = xr0 + DET;
    const bool r1ok = (row_g0 + 1) < nrows;

    for (int e = tid; e < NPAIR; e += THREADS) {
        int base = ((e & 7) * PITCH) + (e >> 3);
        int p0 = 2 * e - 737;
        int p1 = p0 + 1;
        float w0 = 0.05f * __cosf(((float)p0 - 367.5f) * kk);
        float w1 = 0.05f * __cosf(((float)p1 - 367.5f) * kk);
        bool v0ok = (p0 >= 0) & (p0 < DET);
        bool v1ok = (p1 >= 0) & (p1 < DET);
        float a0 = v0ok ? xr0[p0] * w0 : 0.0f;
        float a1 = v1ok ? xr0[p1] * w1 : 0.0f;
        xs2[base] = pk2(a0, a1);
        float b0 = (v0ok && r1ok) ? xr1[p0] * w0 : 0.0f;
        float b1 = (v1ok && r1ok) ? xr1[p1] * w1 : 0.0f;
        xs2[ROWSTRIDE + base] = pk2(b0, b1);
    }
    __syncthreads();

    const int row = tid / TPR;            // 0 or 1
    const int tl  = tid - row * TPR;      // thread-in-row
    const u64* wbase = &xs2[row * ROWSTRIDE + tl];
    const float fc = g_fc;

    // ---- init accumulators with center tap ----
    u64 acc[8];
#pragma unroll
    for (int q = 0; q < 8; ++q) {
        int h0 = 368 + q, h1 = 369 + q;
        float a = fc * ((const float*)&wbase[(h0 & 7) * PITCH + (h0 >> 3)])[1];
        float b = fc * ((const float*)&wbase[(h1 & 7) * PITCH + (h1 >> 3)])[0];
        acc[q] = pk2(a, b);
    }

    // ---- 16-slot rotating window: w[i] = pair(jb+1+i mod rotation) ----
    u64 w[16];
#pragma unroll
    for (int i = 0; i < 15; ++i) {
        int h = 1 + i;
        w[i] = wbase[(h & 7) * PITCH + (h >> 3)];
    }
    w[15] = 0ull;

    // ---- register double-buffered splatted taps ----
    u64 fa[8], fb[8];
#pragma unroll
    for (int t = 0; t < 8; ++t) {
        fa[t] = __ldg(&g_fz2[t]);
        fb[t] = __ldg(&g_fz2[8 + t]);
    }

    const u64* wk  = wbase;
    const u64* fpt = g_fz2;

#pragma unroll 1
    for (int m = 0; m < NODD / 16; ++m) {
        // ===== half A: taps jb..jb+7 (jb = 16m) =====
        tapstep<0>(fa[0], acc, w);  w[15] = wk[0 * PITCH + 2];  fa[0] = __ldg(fpt + 16);
        tapstep<1>(fa[1], acc, w);  w[0]  = wk[1 * PITCH + 2];  fa[1] = __ldg(fpt + 17);
        tapstep<2>(fa[2], acc, w);  w[1]  = wk[2 * PITCH + 2];  fa[2] = __ldg(fpt + 18);
        tapstep<3>(fa[3], acc, w);  w[2]  = wk[3 * PITCH + 2];  fa[3] = __ldg(fpt + 19);
        tapstep<4>(fa[4], acc, w);  w[3]  = wk[4 * PITCH + 2];  fa[4] = __ldg(fpt + 20);
        tapstep<5>(fa[5], acc, w);  w[4]  = wk[5 * PITCH + 2];  fa[5] = __ldg(fpt + 21);
        tapstep<6>(fa[6], acc, w);  w[5]  = wk[6 * PITCH + 2];  fa[6] = __ldg(fpt + 22);
        tapstep<7>(fa[7], acc, w);  w[6]  = wk[7 * PITCH + 2];  fa[7] = __ldg(fpt + 23);
        // ===== half B: taps jb+8..jb+15 =====
        tapstep<8> (fb[0], acc, w); w[7]  = wk[0 * PITCH + 3];  fb[0] = __ldg(fpt + 24);
        tapstep<9> (fb[1], acc, w); w[8]  = wk[1 * PITCH + 3];  fb[1] = __ldg(fpt + 25);
        tapstep<10>(fb[2], acc, w); w[9]  = wk[2 * PITCH + 3];  fb[2] = __ldg(fpt + 26);
        tapstep<11>(fb[3], acc, w); w[10] = wk[3 * PITCH + 3];  fb[3] = __ldg(fpt + 27);
        tapstep<12>(fb[4], acc, w); w[11] = wk[4 * PITCH + 3];  fb[4] = __ldg(fpt + 28);
        tapstep<13>(fb[5], acc, w); w[12] = wk[5 * PITCH + 3];  fb[5] = __ldg(fpt + 29);
        tapstep<14>(fb[6], acc, w); w[13] = wk[6 * PITCH + 3];  fb[6] = __ldg(fpt + 30);
        tapstep<15>(fb[7], acc, w); w[14] = wk[7 * PITCH + 3];  fb[7] = __ldg(fpt + 31);
        wk  += 2;
        fpt += 16;
    }

    // ---- store 16 outputs as 8 packed u64 ----
    int row_g = row_g0 + row;
    if (row_g < nrows) {
        u64* orow = (u64*)(out + (size_t)row_g * DET);
#pragma unroll
        for (int q = 0; q < 8; ++q) orow[8 * tl + q] = acc[q];
    }
}

extern "C" void kernel_launch(void* const* d_in, const int* in_sizes, int n_in,
                              void* d_out, int out_size) {
    const float* sino  = (const float*)d_in[0];
    const float* filt  = (const float*)d_in[1];
    const int*   scale = (const int*)d_in[2];
    float* out = (float*)d_out;

    int nrows = in_sizes[0] / DET;          // 18432
    int nblk  = (nrows + 1) / 2;            // 2 rows per block

    prep_kernel<<<1, NTAPPAD>>>(filt);
    conv_kernel<<<nblk, THREADS>>>(sino, out, scale, nrows);
}